// round 1
// baseline (speedup 1.0000x reference)
#include <cuda_runtime.h>
#include <cstdint>

// Problem shape (fixed by setup_inputs)
#define BB 64
#define SS 8192
#define EE 32
#define HH 64

typedef unsigned long long u64;

// ---------------- f32x2 helpers (Blackwell packed fp32) ----------------
__device__ __forceinline__ u64 pack2(float x, float y) {
    u64 r; asm("mov.b64 %0, {%1, %2};" : "=l"(r) : "f"(x), "f"(y)); return r;
}
__device__ __forceinline__ u64 dup2(float x) {
    u64 r; asm("mov.b64 %0, {%1, %1};" : "=l"(r) : "f"(x)); return r;
}
__device__ __forceinline__ void unpack2(u64 v, float& x, float& y) {
    asm("mov.b64 {%0, %1}, %2;" : "=f"(x), "=f"(y) : "l"(v));
}
__device__ __forceinline__ u64 ffma2(u64 a, u64 b, u64 c) {
    u64 d; asm("fma.rn.f32x2 %0, %1, %2, %3;" : "=l"(d) : "l"(a), "l"(b), "l"(c)); return d;
}

__device__ __forceinline__ float silu_f(float v) {
    return v / (1.0f + __expf(-v));
}

// ---------------- scratch (static device memory; no allocations) ----------------
__device__ float g_q[(size_t)BB * SS * EE];   // 64 MB intermediate q = silu(x@Qw^T)
__device__ float g_rnorm[BB * EE];            // 1 / max(||q[:,f]||, eps)

// =======================================================================
// K1: q[b,s,f] = silu( sum_e x[b,s,e] * Qw[f,e] )
// grid (32, 64), block 256 — one row per thread
// =======================================================================
__global__ __launch_bounds__(256) void k1_proj(const float* __restrict__ x,
                                               const float* __restrict__ Qw) {
    // Qs[e*16 + p] = { Qw[2p, e], Qw[2p+1, e] }  (pairs along output dim f)
    __shared__ u64 Qs[EE * 16];
    const int tid = threadIdx.x;
    const int b = blockIdx.y;
    const int s = blockIdx.x * 256 + tid;

    for (int i = tid; i < EE * 16; i += 256) {
        int e = i >> 4, p = i & 15;
        Qs[i] = pack2(Qw[(2 * p) * EE + e], Qw[(2 * p + 1) * EE + e]);
    }
    __syncthreads();

    const size_t row_off = ((size_t)b * SS + s) * EE;
    const float4* xr = (const float4*)(x + row_off);
    float xv[EE];
#pragma unroll
    for (int i = 0; i < EE / 4; i++) {
        float4 t = xr[i];
        xv[4 * i + 0] = t.x; xv[4 * i + 1] = t.y;
        xv[4 * i + 2] = t.z; xv[4 * i + 3] = t.w;
    }

    u64 acc[16];
#pragma unroll
    for (int p = 0; p < 16; p++) acc[p] = 0ull;

#pragma unroll
    for (int e = 0; e < EE; e++) {
        u64 xe = dup2(xv[e]);
        const u64* qrow = &Qs[e * 16];
#pragma unroll
        for (int p = 0; p < 16; p += 2) {
            ulonglong2 w = *(const ulonglong2*)&qrow[p];   // LDS.128: two packed pairs
            acc[p]     = ffma2(xe, w.x, acc[p]);
            acc[p + 1] = ffma2(xe, w.y, acc[p + 1]);
        }
    }

    float qv[EE];
#pragma unroll
    for (int p = 0; p < 16; p++) unpack2(acc[p], qv[2 * p], qv[2 * p + 1]);
#pragma unroll
    for (int i = 0; i < EE; i++) qv[i] = silu_f(qv[i]);

    float4* qo = (float4*)(g_q + row_off);
#pragma unroll
    for (int i = 0; i < EE / 4; i++)
        qo[i] = make_float4(qv[4 * i], qv[4 * i + 1], qv[4 * i + 2], qv[4 * i + 3]);
}

// =======================================================================
// K2: rnorm[b,f] = 1 / max( sqrt( sum_s q[b,s,f]^2 ), 1e-12 )
// grid 64, block 256 (32 row-groups x 8 float4-lanes). Fully deterministic.
// =======================================================================
__global__ __launch_bounds__(256) void k2_norm() {
    const int tid = threadIdx.x;
    const int b = blockIdx.x;
    const int f4 = tid & 7;      // which float4 chunk of the 32-wide row
    const int g  = tid >> 3;     // row group (32 groups)

    const float4* qb = (const float4*)(g_q + (size_t)b * SS * EE);
    float4 a = make_float4(0.f, 0.f, 0.f, 0.f);
#pragma unroll 4
    for (int s = g; s < SS; s += 32) {
        float4 v = qb[(size_t)s * 8 + f4];
        a.x = fmaf(v.x, v.x, a.x);
        a.y = fmaf(v.y, v.y, a.y);
        a.z = fmaf(v.z, v.z, a.z);
        a.w = fmaf(v.w, v.w, a.w);
    }

    __shared__ float4 sp[256];
    sp[tid] = a;
    __syncthreads();

    if (tid < 8) {
        float4 r = make_float4(0.f, 0.f, 0.f, 0.f);
        for (int gg = 0; gg < 32; gg++) {
            float4 v = sp[gg * 8 + tid];
            r.x += v.x; r.y += v.y; r.z += v.z; r.w += v.w;
        }
        const int base = b * EE + tid * 4;
        g_rnorm[base + 0] = 1.0f / fmaxf(sqrtf(r.x), 1e-12f);
        g_rnorm[base + 1] = 1.0f / fmaxf(sqrtf(r.y), 1e-12f);
        g_rnorm[base + 2] = 1.0f / fmaxf(sqrtf(r.z), 1e-12f);
        g_rnorm[base + 3] = 1.0f / fmaxf(sqrtf(r.w), 1e-12f);
    }
}

// =======================================================================
// K3: qn = q * rnorm;  h = silu(qn @ W1_b^T + b1_b);  out = h @ W2_b^T + b2_b
// h is never materialized: each h_j is folded into the out accumulators.
// grid (32, 64), block 256 — one row per thread
// =======================================================================
__global__ __launch_bounds__(256) void k3_mlp(const float* __restrict__ W1,
                                              const float* __restrict__ b1,
                                              const float* __restrict__ W2,
                                              const float* __restrict__ b2,
                                              float* __restrict__ out) {
    // W1s[jp*32 + e]  = { W1[b, 2jp,   e], W1[b, 2jp+1, e] }   (pairs along h dim)
    // W2s[j*16 + ep]  = { W2[b, 2ep,   j], W2[b, 2ep+1, j] }   (pairs along e dim)
    __shared__ u64 W1s[32 * EE];
    __shared__ u64 W2s[HH * 16];
    __shared__ u64 b1s[32];
    __shared__ u64 b2s[16];
    __shared__ float rns[EE];

    const int tid = threadIdx.x;
    const int b = blockIdx.y;
    const int s = blockIdx.x * 256 + tid;

    const float* W1b = W1 + (size_t)b * HH * EE;
    const float* W2b = W2 + (size_t)b * EE * HH;

    for (int i = tid; i < 32 * EE; i += 256) {
        int jp = i >> 5, e = i & 31;
        W1s[i] = pack2(W1b[(2 * jp) * EE + e], W1b[(2 * jp + 1) * EE + e]);
    }
    for (int i = tid; i < HH * 16; i += 256) {
        int j = i >> 4, ep = i & 15;
        W2s[i] = pack2(W2b[(2 * ep) * HH + j], W2b[(2 * ep + 1) * HH + j]);
    }
    if (tid < 32) {
        b1s[tid] = pack2(b1[b * HH + 2 * tid], b1[b * HH + 2 * tid + 1]);
        rns[tid] = g_rnorm[b * EE + tid];
    }
    if (tid < 16) {
        b2s[tid] = pack2(b2[b * EE + 2 * tid], b2[b * EE + 2 * tid + 1]);
    }
    __syncthreads();

    const size_t row_off = ((size_t)b * SS + s) * EE;
    const float4* qr = (const float4*)(g_q + row_off);
    float qv[EE];
#pragma unroll
    for (int i = 0; i < EE / 4; i++) {
        float4 t = qr[i];
        qv[4 * i + 0] = t.x; qv[4 * i + 1] = t.y;
        qv[4 * i + 2] = t.z; qv[4 * i + 3] = t.w;
    }
#pragma unroll
    for (int e = 0; e < EE; e++) qv[e] *= rns[e];

    u64 qd[EE];
#pragma unroll
    for (int e = 0; e < EE; e++) qd[e] = dup2(qv[e]);

    u64 oacc[16];
#pragma unroll
    for (int ep = 0; ep < 16; ep++) oacc[ep] = b2s[ep];

#pragma unroll 2
    for (int jp = 0; jp < 32; jp++) {
        u64 h = b1s[jp];
        const u64* w1r = &W1s[jp * EE];
#pragma unroll
        for (int e = 0; e < EE; e += 2) {
            ulonglong2 w = *(const ulonglong2*)&w1r[e];    // LDS.128
            h = ffma2(qd[e],     w.x, h);
            h = ffma2(qd[e + 1], w.y, h);
        }
        float h0, h1;
        unpack2(h, h0, h1);
        u64 s0 = dup2(silu_f(h0));
        u64 s1 = dup2(silu_f(h1));
        const u64* w20 = &W2s[(2 * jp) * 16];
        const u64* w21 = &W2s[(2 * jp + 1) * 16];
#pragma unroll
        for (int ep = 0; ep < 16; ep += 2) {
            ulonglong2 a = *(const ulonglong2*)&w20[ep];   // LDS.128
            ulonglong2 c = *(const ulonglong2*)&w21[ep];   // LDS.128
            oacc[ep]     = ffma2(s0, a.x, oacc[ep]);
            oacc[ep]     = ffma2(s1, c.x, oacc[ep]);
            oacc[ep + 1] = ffma2(s0, a.y, oacc[ep + 1]);
            oacc[ep + 1] = ffma2(s1, c.y, oacc[ep + 1]);
        }
    }

    float ov[EE];
#pragma unroll
    for (int ep = 0; ep < 16; ep++) unpack2(oacc[ep], ov[2 * ep], ov[2 * ep + 1]);

    float4* orow = (float4*)(out + row_off);
#pragma unroll
    for (int i = 0; i < EE / 4; i++)
        orow[i] = make_float4(ov[4 * i], ov[4 * i + 1], ov[4 * i + 2], ov[4 * i + 3]);
}

// =======================================================================
extern "C" void kernel_launch(void* const* d_in, const int* in_sizes, int n_in,
                              void* d_out, int out_size) {
    const float* x  = (const float*)d_in[0];
    const float* Qw = (const float*)d_in[1];
    const float* W1 = (const float*)d_in[2];
    const float* b1 = (const float*)d_in[3];
    const float* W2 = (const float*)d_in[4];
    const float* b2 = (const float*)d_in[5];
    float* out = (float*)d_out;

    dim3 grid(SS / 256, BB);
    k1_proj<<<grid, 256>>>(x, Qw);
    k2_norm<<<BB, 256>>>();
    k3_mlp<<<grid, 256>>>(W1, b1, W2, b2, out);
}

// round 3
// speedup vs baseline: 1.4707x; 1.4707x over previous
#include <cuda_runtime.h>
#include <cstdint>

// Problem shape (fixed by setup_inputs)
#define BB 64
#define SS 8192
#define EE 32
#define HH 64

typedef unsigned long long u64;

// ---------------- f32x2 helpers (Blackwell packed fp32) ----------------
__device__ __forceinline__ u64 pack2(float x, float y) {
    u64 r; asm("mov.b64 %0, {%1, %2};" : "=l"(r) : "f"(x), "f"(y)); return r;
}
__device__ __forceinline__ u64 dup2(float x) {
    u64 r; asm("mov.b64 %0, {%1, %1};" : "=l"(r) : "f"(x)); return r;
}
__device__ __forceinline__ void unpack2(u64 v, float& x, float& y) {
    asm("mov.b64 {%0, %1}, %2;" : "=f"(x), "=f"(y) : "l"(v));
}
__device__ __forceinline__ u64 ffma2(u64 a, u64 b, u64 c) {
    u64 d; asm("fma.rn.f32x2 %0, %1, %2, %3;" : "=l"(d) : "l"(a), "l"(b), "l"(c)); return d;
}
__device__ __forceinline__ float silu_f(float v) {
    return v / (1.0f + __expf(-v));
}

// ---------------- scratch (static device memory; no allocations) ----------------
__device__ float g_q[(size_t)BB * SS * EE];     // 64 MB intermediate q = silu(x@Qw^T)
__device__ float g_partial[BB * 32 * EE];       // per-(b, block) partial sum of squares
__device__ float g_rnorm[BB * EE];              // 1 / max(||q[:,f]||, eps)

// =======================================================================
// K1: q = silu(x @ Qw^T), 256-row tile, 128 threads, 8x8 register tile.
// Also emits deterministic per-block partial sum-of-squares per column f.
// grid (32, 64)
// =======================================================================
__global__ __launch_bounds__(128) void k1_proj(const float* __restrict__ x,
                                               const float* __restrict__ Qw) {
    __shared__ __align__(16) float xs[256][36];   // padded: +4 banks/row
    __shared__ __align__(16) u64   ws[32][16];    // ws[e][fpair]
    __shared__ float red[32][33];

    const int tid = threadIdx.x;
    const int b   = blockIdx.y;
    const int blk = blockIdx.x;
    const size_t base = ((size_t)b * SS + (size_t)blk * 256) * EE;

    // stage x tile (256 x 32 floats = 2048 float4)
    const float4* xsrc = (const float4*)(x + base);
#pragma unroll
    for (int i = 0; i < 16; i++) {
        int idx = tid + i * 128;
        *(float4*)&xs[idx >> 3][(idx & 7) * 4] = xsrc[idx];
    }
    // stage Qw as pairs along the output dim f
#pragma unroll
    for (int j = 0; j < 4; j++) {
        int i = tid + j * 128;
        int e = i >> 4, p = i & 15;
        ws[e][p] = pack2(Qw[(2 * p) * EE + e], Qw[(2 * p + 1) * EE + e]);
    }
    __syncthreads();

    const int rg = tid >> 2;   // 32 row-groups, rows rg + 32*r (interleaved)
    const int cg = tid & 3;    // 4 col-groups, cols 8*cg .. 8*cg+7

    u64 acc[8][4];
#pragma unroll
    for (int r = 0; r < 8; r++)
#pragma unroll
        for (int p = 0; p < 4; p++) acc[r][p] = 0ull;

#pragma unroll
    for (int k4 = 0; k4 < 8; k4++) {
        float xf[8][4];
#pragma unroll
        for (int r = 0; r < 8; r++)
            *(float4*)xf[r] = *(const float4*)&xs[rg + 32 * r][k4 * 4];
#pragma unroll
        for (int kk = 0; kk < 4; kk++) {
            int k = k4 * 4 + kk;
            ulonglong2 wa = *(const ulonglong2*)&ws[k][cg * 4];
            ulonglong2 wb = *(const ulonglong2*)&ws[k][cg * 4 + 2];
#pragma unroll
            for (int r = 0; r < 8; r++) {
                u64 xd = dup2(xf[r][kk]);
                acc[r][0] = ffma2(xd, wa.x, acc[r][0]);
                acc[r][1] = ffma2(xd, wa.y, acc[r][1]);
                acc[r][2] = ffma2(xd, wb.x, acc[r][2]);
                acc[r][3] = ffma2(xd, wb.y, acc[r][3]);
            }
        }
    }

    // epilogue: silu, store q, accumulate sum of squares per column
    float part[8];
#pragma unroll
    for (int c = 0; c < 8; c++) part[c] = 0.0f;

#pragma unroll
    for (int r = 0; r < 8; r++) {
        float v[8];
#pragma unroll
        for (int p = 0; p < 4; p++) unpack2(acc[r][p], v[2 * p], v[2 * p + 1]);
#pragma unroll
        for (int c = 0; c < 8; c++) {
            float s = silu_f(v[c]);
            v[c] = s;
            part[c] = fmaf(s, s, part[c]);
        }
        int row = rg + 32 * r;
        float* dst = g_q + base + (size_t)row * EE + cg * 8;
        *(float4*)dst       = make_float4(v[0], v[1], v[2], v[3]);
        *(float4*)(dst + 4) = make_float4(v[4], v[5], v[6], v[7]);
    }
#pragma unroll
    for (int c = 0; c < 8; c++) red[rg][cg * 8 + c] = part[c];
    __syncthreads();

    if (tid < 32) {
        float s = 0.0f;
#pragma unroll
        for (int i = 0; i < 32; i++) s += red[i][tid];
        g_partial[(b * 32 + blk) * EE + tid] = s;
    }
}

// =======================================================================
// K2: reduce 32 block partials -> rnorm. grid 64, block 32. Deterministic.
// =======================================================================
__global__ void k2_norm() {
    const int b = blockIdx.x;
    const int f = threadIdx.x;
    float s = 0.0f;
#pragma unroll
    for (int i = 0; i < 32; i++) s += g_partial[(b * 32 + i) * EE + f];
    g_rnorm[b * EE + f] = 1.0f / fmaxf(sqrtf(s), 1e-12f);
}

// =======================================================================
// K3: h = silu(q @ (rnorm o W1)^T + b1); out = h @ W2^T + b2
// 128-row tile, 128 threads. Stage1: 8x8 tile; Stage2: 8x4 tile.
// rnorm folded into W1 columns at staging. grid (64, 64), dynamic smem.
// =======================================================================
__global__ __launch_bounds__(128) void k3_mlp(const float* __restrict__ W1,
                                              const float* __restrict__ b1,
                                              const float* __restrict__ W2,
                                              const float* __restrict__ b2,
                                              float* __restrict__ out) {
    extern __shared__ __align__(16) char sm[];
    float (*qs)[36]  = (float (*)[36])(sm);                // 128*36*4  = 18432
    float (*hs)[68]  = (float (*)[68])(sm + 18432);        // 128*68*4  = 34816
    u64   (*w1s)[32] = (u64 (*)[32])(sm + 53248);          // [e][hpair] 32*32*8 = 8192
    u64   (*w2s)[16] = (u64 (*)[16])(sm + 61440);          // [h][epair] 64*16*8 = 8192
    u64* b1s = (u64*)(sm + 69632);                         // 32*8 = 256
    u64* b2s = (u64*)(sm + 69888);                         // 16*8 = 128  -> total 70016

    const int tid = threadIdx.x;
    const int b   = blockIdx.y;
    const int blk = blockIdx.x;
    const size_t base = ((size_t)b * SS + (size_t)blk * 128) * EE;

    // --- stage q tile (128 x 32 = 1024 float4) ---
    const float4* qsrc = (const float4*)(g_q + base);
#pragma unroll
    for (int i = 0; i < 8; i++) {
        int idx = tid + i * 128;
        *(float4*)&qs[idx >> 3][(idx & 7) * 4] = qsrc[idx];
    }
    // --- stage W1 * rnorm as pairs along h ---
    const float* W1b = W1 + (size_t)b * HH * EE;
    const float* rn  = g_rnorm + b * EE;
#pragma unroll
    for (int j = 0; j < 8; j++) {
        int i = tid + j * 128;         // 0..1023
        int e = i >> 5, hp = i & 31;
        float r = rn[e];
        w1s[e][hp] = pack2(W1b[(2 * hp) * EE + e] * r, W1b[(2 * hp + 1) * EE + e] * r);
    }
    // --- stage W2 as pairs along e ---
    const float* W2b = W2 + (size_t)b * EE * HH;
#pragma unroll
    for (int j = 0; j < 8; j++) {
        int i = tid + j * 128;
        int h = i >> 4, ep = i & 15;
        w2s[h][ep] = pack2(W2b[(2 * ep) * HH + h], W2b[(2 * ep + 1) * HH + h]);
    }
    if (tid < 32) b1s[tid] = pack2(b1[b * HH + 2 * tid], b1[b * HH + 2 * tid + 1]);
    if (tid < 16) b2s[tid] = pack2(b2[b * EE + 2 * tid], b2[b * EE + 2 * tid + 1]);
    __syncthreads();

    // ---------------- stage 1: h tile (128 x 64) ----------------
    {
        const int rg = tid >> 3;   // 16 row-groups, rows rg + 16*r
        const int cg = tid & 7;    // 8 col-groups, h cols 8*cg .. 8*cg+7
        u64 acc[8][4];
#pragma unroll
        for (int r = 0; r < 8; r++)
#pragma unroll
            for (int p = 0; p < 4; p++) acc[r][p] = b1s[cg * 4 + p];

#pragma unroll
        for (int k4 = 0; k4 < 8; k4++) {
            float xf[8][4];
#pragma unroll
            for (int r = 0; r < 8; r++)
                *(float4*)xf[r] = *(const float4*)&qs[rg + 16 * r][k4 * 4];
#pragma unroll
            for (int kk = 0; kk < 4; kk++) {
                int k = k4 * 4 + kk;
                ulonglong2 wa = *(const ulonglong2*)&w1s[k][cg * 4];
                ulonglong2 wb = *(const ulonglong2*)&w1s[k][cg * 4 + 2];
#pragma unroll
                for (int r = 0; r < 8; r++) {
                    u64 xd = dup2(xf[r][kk]);
                    acc[r][0] = ffma2(xd, wa.x, acc[r][0]);
                    acc[r][1] = ffma2(xd, wa.y, acc[r][1]);
                    acc[r][2] = ffma2(xd, wb.x, acc[r][2]);
                    acc[r][3] = ffma2(xd, wb.y, acc[r][3]);
                }
            }
        }
#pragma unroll
        for (int r = 0; r < 8; r++) {
            float v[8];
#pragma unroll
            for (int p = 0; p < 4; p++) unpack2(acc[r][p], v[2 * p], v[2 * p + 1]);
#pragma unroll
            for (int c = 0; c < 8; c++) v[c] = silu_f(v[c]);
            int row = rg + 16 * r;
            *(float4*)&hs[row][cg * 8]     = make_float4(v[0], v[1], v[2], v[3]);
            *(float4*)&hs[row][cg * 8 + 4] = make_float4(v[4], v[5], v[6], v[7]);
        }
    }
    __syncthreads();

    // ---------------- stage 2: out tile (128 x 32) ----------------
    {
        const int rg = tid >> 3;   // 16 row-groups, rows rg + 16*r
        const int cg = tid & 7;    // 8 col-groups, e cols 4*cg .. 4*cg+3
        u64 acc[8][2];
#pragma unroll
        for (int r = 0; r < 8; r++) {
            acc[r][0] = b2s[cg * 2];
            acc[r][1] = b2s[cg * 2 + 1];
        }

#pragma unroll
        for (int k4 = 0; k4 < 16; k4++) {
            float xf[8][4];
#pragma unroll
            for (int r = 0; r < 8; r++)
                *(float4*)xf[r] = *(const float4*)&hs[rg + 16 * r][k4 * 4];
#pragma unroll
            for (int kk = 0; kk < 4; kk++) {
                int k = k4 * 4 + kk;
                ulonglong2 w = *(const ulonglong2*)&w2s[k][cg * 2];
#pragma unroll
                for (int r = 0; r < 8; r++) {
                    u64 xd = dup2(xf[r][kk]);
                    acc[r][0] = ffma2(xd, w.x, acc[r][0]);
                    acc[r][1] = ffma2(xd, w.y, acc[r][1]);
                }
            }
        }
#pragma unroll
        for (int r = 0; r < 8; r++) {
            float v[4];
            unpack2(acc[r][0], v[0], v[1]);
            unpack2(acc[r][1], v[2], v[3]);
            int row = rg + 16 * r;
            *(float4*)(out + base + (size_t)row * EE + cg * 4) =
                make_float4(v[0], v[1], v[2], v[3]);
        }
    }
}

// =======================================================================
extern "C" void kernel_launch(void* const* d_in, const int* in_sizes, int n_in,
                              void* d_out, int out_size) {
    const float* x  = (const float*)d_in[0];
    const float* Qw = (const float*)d_in[1];
    const float* W1 = (const float*)d_in[2];
    const float* b1 = (const float*)d_in[3];
    const float* W2 = (const float*)d_in[4];
    const float* b2 = (const float*)d_in[5];
    float* out = (float*)d_out;

    // cheap host-side call; runs during capture only (graph replays skip host code)
    cudaFuncSetAttribute(k3_mlp, cudaFuncAttributeMaxDynamicSharedMemorySize, 70016);

    k1_proj<<<dim3(SS / 256, BB), 128>>>(x, Qw);
    k2_norm<<<BB, 32>>>();
    k3_mlp<<<dim3(SS / 128, BB), 128, 70016>>>(W1, b1, W2, b2, out);
}